// round 10
// baseline (speedup 1.0000x reference)
#include <cuda_runtime.h>

// y[b,c,s] = sum_{k=0..127} (kr[c,k] + i*ki[c,k]) * x[b, (s*128 - k) mod 16000]
// Reference output: complex64 (B=32, C=40, S=125).
// Output lowering is selected at runtime from out_size:
//   out_size == B*C*S      (160000): float32 real part only, shape (B,C,S)
//   out_size == 2*B*C*S    (320000): float32 planar stack([re, im]) -> (2,B,C,S)
//   otherwise                       : interleaved float2 (complex64 bytes)

#define LSZ     16000
#define STRIDEH 128
#define BATCH   32
#define CHANS   40
#define KTAPS   128
#define SOUT    125
#define S_PER_BLK 32
#define GROUPS  4
#define NTHREADS 256
#define XT_PITCH 33          // 32 lanes + 1 pad word -> conflict-free
#define NOUT    (BATCH * CHANS * SOUT)   // 160000 complex outputs

// dynamic smem: 40*128 float2 kernels (40960 B) + xT[128][33] (16896 B)
#define SMEM_BYTES ((CHANS * KTAPS) * 8 + (KTAPS * XT_PITCH) * 4)

__global__ __launch_bounds__(NTHREADS, 2)
void ISAC_33062658244828_kernel(const float* __restrict__ x,
                                const float* __restrict__ kr,
                                const float* __restrict__ ki,
                                float* __restrict__ out,
                                int mode)
{
    extern __shared__ float smem[];
    float2* skern = reinterpret_cast<float2*>(smem);        // [c*128 + k]
    float*  xT    = smem + 2 * CHANS * KTAPS;               // [j*33 + lane]

    const int g   = blockIdx.x;     // s-group (0..3)
    const int b   = blockIdx.y;     // batch
    const int tid = threadIdx.x;

    // kernels: coalesced global read, interleaved (kr,ki) in smem
    for (int i = tid; i < CHANS * KTAPS; i += NTHREADS)
        skern[i] = make_float2(kr[i], ki[i]);

    // x segment, transposed: lane l's window (s = g*32+l) is the disjoint
    // chunk x[base + l*128 .. +127], base = g*4096 - 127; stored xT[j][l].
    const int base = g * (S_PER_BLK * STRIDEH) - (KTAPS - 1);
    const float* xb = x + b * LSZ;
    for (int i = tid; i < S_PER_BLK * KTAPS; i += NTHREADS) {
        int idx = base + i;
        if (idx < 0)         idx += LSZ;    // wrap (circular conv, g=0)
        else if (idx >= LSZ) idx -= LSZ;    // wrap (g=3 unused tail lanes)
        const int l = i >> 7;
        const int j = i & 127;
        xT[j * XT_PITCH + l] = xb[idx];
    }
    __syncthreads();

    const int w  = tid >> 5;        // warp -> channels w*5 .. w*5+4
    const int l  = tid & 31;        // lane = s within group
    const int c0 = w * 5;

    float accr[5] = {0.f, 0.f, 0.f, 0.f, 0.f};
    float acci[5] = {0.f, 0.f, 0.f, 0.f, 0.f};

    const float2* kb = skern + c0 * KTAPS;
    const float*  xl = xT + l;

    // tap k pairs with xT[127 - k][l]
    #pragma unroll 4
    for (int k = 0; k < KTAPS; k += 4) {
        const float x3 = xl[(127 - k) * XT_PITCH];
        const float x2 = xl[(126 - k) * XT_PITCH];
        const float x1 = xl[(125 - k) * XT_PITCH];
        const float x0 = xl[(124 - k) * XT_PITCH];
        #pragma unroll
        for (int j = 0; j < 5; j++) {
            // uniform address across warp -> LDS broadcast, conflict-free
            const float4* kp = reinterpret_cast<const float4*>(kb + j * KTAPS + k);
            const float4 p0 = kp[0];
            const float4 p1 = kp[1];
            accr[j] = fmaf(p0.x, x3, accr[j]);
            acci[j] = fmaf(p0.y, x3, acci[j]);
            accr[j] = fmaf(p0.z, x2, accr[j]);
            acci[j] = fmaf(p0.w, x2, acci[j]);
            accr[j] = fmaf(p1.x, x1, accr[j]);
            acci[j] = fmaf(p1.y, x1, acci[j]);
            accr[j] = fmaf(p1.z, x0, accr[j]);
            acci[j] = fmaf(p1.w, x0, acci[j]);
        }
    }

    const int sg = g * S_PER_BLK + l;
    if (sg < SOUT) {
        const size_t idx0 = (size_t)(b * CHANS + c0) * SOUT + sg;
        if (mode == 0) {                     // real part only (B,C,S)
            #pragma unroll
            for (int j = 0; j < 5; j++)
                out[idx0 + (size_t)j * SOUT] = accr[j];
        } else if (mode == 1) {              // planar (2,B,C,S): re block, im block
            #pragma unroll
            for (int j = 0; j < 5; j++) {
                out[idx0 + (size_t)j * SOUT]        = accr[j];
                out[NOUT + idx0 + (size_t)j * SOUT] = acci[j];
            }
        } else {                             // interleaved complex64
            float2* o2 = reinterpret_cast<float2*>(out);
            #pragma unroll
            for (int j = 0; j < 5; j++)
                o2[idx0 + (size_t)j * SOUT] = make_float2(accr[j], acci[j]);
        }
    }
}

extern "C" void kernel_launch(void* const* d_in, const int* in_sizes, int n_in,
                              void* d_out, int out_size)
{
    // Round-9 evidence: identical rel_err across binding variants proves x is
    // at d_in[0] (dict order). Bind directly.
    const float* x  = (const float*)d_in[0];   // (32, 1, 16000) f32
    const float* kr = (const float*)d_in[1];   // (40, 128) f32
    const float* ki = (const float*)d_in[2];   // (40, 128) f32
    float* out = (float*)d_out;

    // Select output lowering from out_size. Interleaved float2 (mode 2) is
    // experimentally eliminated for the 160000/320000 interpretations, so:
    //   160000 elems -> real-part-only float32
    //   320000 elems -> planar stack([re, im], axis=0)
    //   anything else -> interleaved complex64 fallback
    int mode;
    if (out_size == NOUT)            mode = 0;
    else if (out_size == 2 * NOUT)   mode = 1;
    else                             mode = 2;

    cudaFuncSetAttribute(ISAC_33062658244828_kernel,
                         cudaFuncAttributeMaxDynamicSharedMemorySize, SMEM_BYTES);

    dim3 grid(GROUPS, BATCH);
    ISAC_33062658244828_kernel<<<grid, NTHREADS, SMEM_BYTES>>>(x, kr, ki, out, mode);
}

// round 12
// speedup vs baseline: 1.2389x; 1.2389x over previous
#include <cuda_runtime.h>

// y[b,c,s] = sum_{k=0..127} (kr[c,k] + i*ki[c,k]) * x[b, (s*128 - k) mod 16000]
// Reference output: complex64 (B=32, C=40, S=125); lowering chosen by out_size:
//   out_size == B*C*S   (160000): float32 real part, (B,C,S)
//   out_size == 2*B*C*S (320000): float32 planar stack([re,im]) -> (2,B,C,S)
//   otherwise                   : interleaved float2 (complex64 bytes)

#define LSZ     16000
#define STRIDEH 128
#define BATCH   32
#define CHANS   40
#define KTAPS   128
#define SOUT    125
#define S_PER_BLK 32
#define GROUPS  4
#define NTHREADS 640          // 20 warps, 2 channels per warp
#define XT_PITCH 33           // 32 lanes + 1 pad -> conflict-free scalar LDS
#define NOUT    (BATCH * CHANS * SOUT)

// smem: 40*128 float2 kernels (40960 B) + xT[128][33] floats (16896 B)
#define SMEM_BYTES ((CHANS * KTAPS) * 8 + (KTAPS * XT_PITCH) * 4)

typedef unsigned long long u64;

__device__ __forceinline__ u64 pack2(float v) {
    u64 r;
    asm("mov.b64 %0, {%1, %1};" : "=l"(r) : "f"(v));
    return r;
}
__device__ __forceinline__ void ffma2(u64& acc, u64 a, u64 b) {
    // acc = a * b + acc  (elementwise f32x2) — Blackwell packed FFMA2
    asm("fma.rn.f32x2 %0, %1, %2, %0;" : "+l"(acc) : "l"(a), "l"(b));
}
__device__ __forceinline__ u64 add2(u64 a, u64 b) {
    u64 r;
    asm("add.rn.f32x2 %0, %1, %2;" : "=l"(r) : "l"(a), "l"(b));
    return r;
}

__global__ __launch_bounds__(NTHREADS, 1)
void ISAC_33062658244828_kernel(const float* __restrict__ x,
                                const float* __restrict__ kr,
                                const float* __restrict__ ki,
                                float* __restrict__ out,
                                int mode)
{
    extern __shared__ float smem[];
    float2* skern = reinterpret_cast<float2*>(smem);        // [c*128 + k] = (kr,ki)
    float*  xT    = smem + 2 * CHANS * KTAPS;               // [j*33 + lane]

    const int g   = blockIdx.x;     // s-group (0..3)
    const int b   = blockIdx.y;     // batch
    const int tid = threadIdx.x;

    // kernels: coalesced global read, interleaved (kr,ki) float2 in smem —
    // this is exactly the f32x2 multiplicand for the packed FMA below.
    for (int i = tid; i < CHANS * KTAPS; i += NTHREADS)
        skern[i] = make_float2(kr[i], ki[i]);

    // x segment, transposed: lane l's window (s = g*32+l) is the disjoint
    // chunk x[base + l*128 .. +127], base = g*4096 - 127; stored xT[j][l]
    // so scalar LDS at each tap is bank-conflict-free ((j+l) mod 32).
    const int base = g * (S_PER_BLK * STRIDEH) - (KTAPS - 1);
    const float* xb = x + b * LSZ;
    for (int i = tid; i < S_PER_BLK * KTAPS; i += NTHREADS) {
        int idx = base + i;
        if (idx < 0)         idx += LSZ;    // circular wrap (g=0)
        else if (idx >= LSZ) idx -= LSZ;    // wrap for g=3 unused tail lanes
        const int l = i >> 7;
        const int j = i & 127;
        xT[j * XT_PITCH + l] = xb[idx];
    }
    __syncthreads();

    const int w  = tid >> 5;        // warp 0..19 -> channels 2w, 2w+1
    const int l  = tid & 31;        // lane = s within group
    const int c0 = w * 2;

    // 4 independent accumulation chains: {channel} x {even/odd tap pair}
    u64 accA0 = 0, accB0 = 0, accA1 = 0, accB1 = 0;

    const float2* kb0 = skern + (size_t)c0 * KTAPS;
    const float2* kb1 = kb0 + KTAPS;
    const float*  xl  = xT + l;

    // tap k pairs with xT[127 - k][l]
    #pragma unroll 4
    for (int k = 0; k < KTAPS; k += 4) {
        const u64 px0 = pack2(xl[(127 - k) * XT_PITCH]);   // tap k
        const u64 px1 = pack2(xl[(126 - k) * XT_PITCH]);   // tap k+1
        const u64 px2 = pack2(xl[(125 - k) * XT_PITCH]);   // tap k+2
        const u64 px3 = pack2(xl[(124 - k) * XT_PITCH]);   // tap k+3

        // 16B uniform-address LDS.128 broadcast: taps (k,k+1) and (k+2,k+3)
        const ulonglong2 q0 = *reinterpret_cast<const ulonglong2*>(kb0 + k);
        const ulonglong2 q1 = *reinterpret_cast<const ulonglong2*>(kb0 + k + 2);
        const ulonglong2 r0 = *reinterpret_cast<const ulonglong2*>(kb1 + k);
        const ulonglong2 r1 = *reinterpret_cast<const ulonglong2*>(kb1 + k + 2);

        ffma2(accA0, q0.x, px0);   // ch c0,   tap k
        ffma2(accB0, q0.y, px1);   // ch c0,   tap k+1
        ffma2(accA0, q1.x, px2);   // ch c0,   tap k+2
        ffma2(accB0, q1.y, px3);   // ch c0,   tap k+3
        ffma2(accA1, r0.x, px0);   // ch c0+1, tap k
        ffma2(accB1, r0.y, px1);
        ffma2(accA1, r1.x, px2);
        ffma2(accB1, r1.y, px3);
    }

    const u64 acc0 = add2(accA0, accB0);
    const u64 acc1 = add2(accA1, accB1);
    float re0, im0, re1, im1;
    asm("mov.b64 {%0, %1}, %2;" : "=f"(re0), "=f"(im0) : "l"(acc0));
    asm("mov.b64 {%0, %1}, %2;" : "=f"(re1), "=f"(im1) : "l"(acc1));

    const int sg = g * S_PER_BLK + l;
    if (sg < SOUT) {
        const size_t idx0 = (size_t)(b * CHANS + c0) * SOUT + sg;
        if (mode == 0) {                     // real part only (B,C,S)
            out[idx0]        = re0;
            out[idx0 + SOUT] = re1;
        } else if (mode == 1) {              // planar (2,B,C,S)
            out[idx0]               = re0;
            out[idx0 + SOUT]        = re1;
            out[NOUT + idx0]        = im0;
            out[NOUT + idx0 + SOUT] = im1;
        } else {                             // interleaved complex64
            float2* o2 = reinterpret_cast<float2*>(out);
            o2[idx0]        = make_float2(re0, im0);
            o2[idx0 + SOUT] = make_float2(re1, im1);
        }
    }
}

extern "C" void kernel_launch(void* const* d_in, const int* in_sizes, int n_in,
                              void* d_out, int out_size)
{
    const float* x  = (const float*)d_in[0];   // (32, 1, 16000) f32
    const float* kr = (const float*)d_in[1];   // (40, 128) f32
    const float* ki = (const float*)d_in[2];   // (40, 128) f32
    float* out = (float*)d_out;

    int mode;
    if (out_size == NOUT)          mode = 0;
    else if (out_size == 2 * NOUT) mode = 1;
    else                           mode = 2;

    cudaFuncSetAttribute(ISAC_33062658244828_kernel,
                         cudaFuncAttributeMaxDynamicSharedMemorySize, SMEM_BYTES);

    dim3 grid(GROUPS, BATCH);
    ISAC_33062658244828_kernel<<<grid, NTHREADS, SMEM_BYTES>>>(x, kr, ki, out, mode);
}

// round 14
// speedup vs baseline: 1.5525x; 1.2531x over previous
#include <cuda_runtime.h>

// y[b,c,s] = sum_{k=0..127} (kr[c,k] + i*ki[c,k]) * x[b, (s*128 - k) mod 16000]
// Reference output: complex64 (B=32, C=40, S=125); lowering chosen by out_size:
//   out_size == B*C*S   (160000): float32 real part, (B,C,S)
//   out_size == 2*B*C*S (320000): float32 planar stack([re,im]) -> (2,B,C,S)
//   otherwise                   : interleaved float2 (complex64 bytes)

#define LSZ     16000
#define STRIDEH 128
#define BATCH   32
#define CHANS   40
#define KTAPS   128
#define SOUT    125
#define S_PER_BLK 32
#define GROUPS  4
#define NTHREADS 640          // 20 warps, 2 channels per warp
#define XW_PITCH 132          // 128 + 4 floats pad = 33 float4 (odd) -> conflict-free LDS.128
#define NOUT    (BATCH * CHANS * SOUT)

// smem: 40*128 float2 kernels (40960 B) + xw[32][132] floats (16896 B)
#define SMEM_BYTES ((CHANS * KTAPS) * 8 + (S_PER_BLK * XW_PITCH) * 4)

typedef unsigned long long u64;

__device__ __forceinline__ u64 pack2(float v) {
    u64 r;
    asm("mov.b64 %0, {%1, %1};" : "=l"(r) : "f"(v));
    return r;
}
__device__ __forceinline__ void ffma2(u64& acc, u64 a, u64 b) {
    // acc = a * b + acc  (elementwise f32x2) — Blackwell packed FFMA2
    asm("fma.rn.f32x2 %0, %1, %2, %0;" : "+l"(acc) : "l"(a), "l"(b));
}
__device__ __forceinline__ u64 add2(u64 a, u64 b) {
    u64 r;
    asm("add.rn.f32x2 %0, %1, %2;" : "=l"(r) : "l"(a), "l"(b));
    return r;
}

__global__ __launch_bounds__(NTHREADS, 1)
void ISAC_33062658244828_kernel(const float* __restrict__ x,
                                const float* __restrict__ kr,
                                const float* __restrict__ ki,
                                float* __restrict__ out,
                                int mode)
{
    extern __shared__ float smem[];
    float2* skern = reinterpret_cast<float2*>(smem);        // [c*128 + k] = (kr,ki)
    float*  xw    = smem + 2 * CHANS * KTAPS;               // [l*132 + j], j = tap index

    const int g   = blockIdx.x;     // s-group (0..3)
    const int b   = blockIdx.y;     // batch
    const int tid = threadIdx.x;

    // --- x windows, reversed so index j == tap k ---
    // lane l's window (s = g*32+l): xw[l][j] = x[(s*128 - j) mod L].
    // Issued first so its LDGs overlap the kernel-table LDGs below.
    const int base = g * (S_PER_BLK * STRIDEH);   // s0 * 128
    const float* xb = x + b * LSZ;
    #pragma unroll
    for (int t = 0; t < (S_PER_BLK * KTAPS) / NTHREADS + 1; t++) {
        const int i = t * NTHREADS + tid;
        if (i < S_PER_BLK * KTAPS) {
            const int l = i >> 7;
            const int j = i & 127;
            int idx = base + l * STRIDEH - j;
            if (idx < 0)         idx += LSZ;   // circular wrap (g=0)
            else if (idx >= LSZ) idx -= LSZ;   // wrap for g=3 unused tail lanes
            xw[l * XW_PITCH + j] = xb[idx];
        }
    }

    // --- kernel table: float4 global reads, interleave to (kr,ki) pairs ---
    // sk4[2i], sk4[2i+1] hold taps 4i..4i+3 of one channel as (re,im) pairs.
    {
        const float4* kr4 = reinterpret_cast<const float4*>(kr);
        const float4* ki4 = reinterpret_cast<const float4*>(ki);
        float4* sk4 = reinterpret_cast<float4*>(skern);
        #pragma unroll
        for (int t = 0; t < (CHANS * KTAPS / 4) / NTHREADS; t++) {
            const int i = t * NTHREADS + tid;
            const float4 a = kr4[i];
            const float4 c = ki4[i];
            sk4[2 * i]     = make_float4(a.x, c.x, a.y, c.y);
            sk4[2 * i + 1] = make_float4(a.z, c.z, a.w, c.w);
        }
    }
    __syncthreads();

    const int w  = tid >> 5;        // warp 0..19 -> channels 2w, 2w+1
    const int l  = tid & 31;        // lane = s within group
    const int c0 = w * 2;

    // 4 independent accumulation chains: {channel} x {even/odd tap pair}
    u64 accA0 = 0, accB0 = 0, accA1 = 0, accB1 = 0;

    const float2* kb0 = skern + (size_t)c0 * KTAPS;
    const float2* kb1 = kb0 + KTAPS;
    const float4* xl4 = reinterpret_cast<const float4*>(xw + l * XW_PITCH);

    // 4 taps per iteration: 1 LDS.128 (x, conflict-free) + 4 LDS.128
    // (kernels, uniform-address broadcast) + 8 FFMA2.
    #pragma unroll 4
    for (int k4 = 0; k4 < KTAPS / 4; k4++) {
        const float4 xv = xl4[k4];                 // taps 4k4 .. 4k4+3
        const ulonglong2 q0 = *reinterpret_cast<const ulonglong2*>(kb0 + 4 * k4);
        const ulonglong2 q1 = *reinterpret_cast<const ulonglong2*>(kb0 + 4 * k4 + 2);
        const ulonglong2 r0 = *reinterpret_cast<const ulonglong2*>(kb1 + 4 * k4);
        const ulonglong2 r1 = *reinterpret_cast<const ulonglong2*>(kb1 + 4 * k4 + 2);

        const u64 p0 = pack2(xv.x);
        const u64 p1 = pack2(xv.y);
        const u64 p2 = pack2(xv.z);
        const u64 p3 = pack2(xv.w);

        ffma2(accA0, q0.x, p0);    // ch c0,   tap 4k4
        ffma2(accB0, q0.y, p1);    // ch c0,   tap 4k4+1
        ffma2(accA0, q1.x, p2);
        ffma2(accB0, q1.y, p3);
        ffma2(accA1, r0.x, p0);    // ch c0+1
        ffma2(accB1, r0.y, p1);
        ffma2(accA1, r1.x, p2);
        ffma2(accB1, r1.y, p3);
    }

    const u64 acc0 = add2(accA0, accB0);
    const u64 acc1 = add2(accA1, accB1);
    float re0, im0, re1, im1;
    asm("mov.b64 {%0, %1}, %2;" : "=f"(re0), "=f"(im0) : "l"(acc0));
    asm("mov.b64 {%0, %1}, %2;" : "=f"(re1), "=f"(im1) : "l"(acc1));

    const int sg = g * S_PER_BLK + l;
    if (sg < SOUT) {
        const size_t idx0 = (size_t)(b * CHANS + c0) * SOUT + sg;
        if (mode == 0) {                     // real part only (B,C,S)
            out[idx0]        = re0;
            out[idx0 + SOUT] = re1;
        } else if (mode == 1) {              // planar (2,B,C,S)
            out[idx0]               = re0;
            out[idx0 + SOUT]        = re1;
            out[NOUT + idx0]        = im0;
            out[NOUT + idx0 + SOUT] = im1;
        } else {                             // interleaved complex64
            float2* o2 = reinterpret_cast<float2*>(out);
            o2[idx0]        = make_float2(re0, im0);
            o2[idx0 + SOUT] = make_float2(re1, im1);
        }
    }
}

extern "C" void kernel_launch(void* const* d_in, const int* in_sizes, int n_in,
                              void* d_out, int out_size)
{
    const float* x  = (const float*)d_in[0];   // (32, 1, 16000) f32
    const float* kr = (const float*)d_in[1];   // (40, 128) f32
    const float* ki = (const float*)d_in[2];   // (40, 128) f32
    float* out = (float*)d_out;

    int mode;
    if (out_size == NOUT)          mode = 0;
    else if (out_size == 2 * NOUT) mode = 1;
    else                           mode = 2;

    cudaFuncSetAttribute(ISAC_33062658244828_kernel,
                         cudaFuncAttributeMaxDynamicSharedMemorySize, SMEM_BYTES);

    dim3 grid(GROUPS, BATCH);
    ISAC_33062658244828_kernel<<<grid, NTHREADS, SMEM_BYTES>>>(x, kr, ki, out, mode);
}

// round 15
// speedup vs baseline: 1.5968x; 1.0286x over previous
#include <cuda_runtime.h>

// y[b,c,s] = sum_{k=0..127} (kr[c,k] + i*ki[c,k]) * x[b, (s*128 - k) mod 16000]
// Reference output: complex64 (B=32, C=40, S=125); lowering chosen by out_size:
//   out_size == B*C*S   (160000): float32 real part, (B,C,S)
//   out_size == 2*B*C*S (320000): float32 planar stack([re,im]) -> (2,B,C,S)
//   otherwise                   : interleaved float2 (complex64 bytes)

#define LSZ      16000
#define STRIDEH  128
#define BATCH    32
#define CHANS    40
#define KTAPS    128
#define SOUT     125
#define S_PER_BLK 32
#define GROUPS   4
#define CH_SPLIT 2
#define CH_PER_CTA (CHANS / CH_SPLIT)     // 20
#define NTHREADS 320                      // 10 warps x 2 channels
#define XW_PITCH 132                      // 33 float4 (odd) -> conflict-free LDS.128
#define NOUT     (BATCH * CHANS * SOUT)

// smem: kr[20][128] + ki[20][128] (20480 B) + xw[32][132] (16896 B) = 37376 B
#define SMEM_BYTES ((2 * CH_PER_CTA * KTAPS + S_PER_BLK * XW_PITCH) * 4)

typedef unsigned long long u64;

__device__ __forceinline__ void ffma2(u64& acc, u64 a, u64 b) {
    // acc = a * b + acc (elementwise f32x2) — Blackwell packed FFMA2
    asm("fma.rn.f32x2 %0, %1, %2, %0;" : "+l"(acc) : "l"(a), "l"(b));
}
__device__ __forceinline__ u64 add2(u64 a, u64 b) {
    u64 r;
    asm("add.rn.f32x2 %0, %1, %2;" : "=l"(r) : "l"(a), "l"(b));
    return r;
}
__device__ __forceinline__ float hsum2(u64 p) {
    float lo, hi;
    asm("mov.b64 {%0, %1}, %2;" : "=f"(lo), "=f"(hi) : "l"(p));
    return lo + hi;
}

__global__ __launch_bounds__(NTHREADS, 2)
void ISAC_33062658244828_kernel(const float* __restrict__ x,
                                const float* __restrict__ kr,
                                const float* __restrict__ ki,
                                float* __restrict__ out,
                                int mode)
{
    extern __shared__ float smem[];
    float* skr = smem;                              // [c][k], c local 0..19
    float* ski = smem + CH_PER_CTA * KTAPS;
    float* xw  = smem + 2 * CH_PER_CTA * KTAPS;     // [l][j], j reversed: x[s*128 - j]

    const int g   = blockIdx.x;          // s-group (0..3)
    const int b   = blockIdx.y;          // batch
    const int h   = blockIdx.z;          // channel half (0: 0..19, 1: 20..39)
    const int tid = threadIdx.x;

    // --- x windows, reversed so smem index j == tap k ---
    // lane l (s = g*32+l): xw[l][j] = x[(s*128 - j) mod L]
    const int base = g * (S_PER_BLK * STRIDEH);
    const float* xb = x + b * LSZ;
    #pragma unroll
    for (int t = 0; t < (S_PER_BLK * KTAPS + NTHREADS - 1) / NTHREADS; t++) {
        const int i = t * NTHREADS + tid;
        if (i < S_PER_BLK * KTAPS) {
            const int l = i >> 7;
            const int j = i & 127;
            int idx = base + l * STRIDEH - j;
            if (idx < 0)         idx += LSZ;   // circular wrap (g=0)
            else if (idx >= LSZ) idx -= LSZ;   // wrap for g=3 unused tail lanes
            xw[l * XW_PITCH + j] = xb[idx];
        }
    }

    // --- kernel halves: straight float4 copy, natural tap layout ---
    {
        const float4* kr4 = reinterpret_cast<const float4*>(kr + h * CH_PER_CTA * KTAPS);
        const float4* ki4 = reinterpret_cast<const float4*>(ki + h * CH_PER_CTA * KTAPS);
        float4* sr4 = reinterpret_cast<float4*>(skr);
        float4* si4 = reinterpret_cast<float4*>(ski);
        #pragma unroll
        for (int t = 0; t < (CH_PER_CTA * KTAPS / 4) / NTHREADS; t++) {
            const int i = t * NTHREADS + tid;
            sr4[i] = kr4[i];
            si4[i] = ki4[i];
        }
    }
    __syncthreads();

    const int w  = tid >> 5;             // warp 0..9 -> local channels 2w, 2w+1
    const int l  = tid & 31;             // lane = s within group
    const int c0 = w * 2;

    const float* k0r = skr + c0 * KTAPS;
    const float* k1r = k0r + KTAPS;
    const float* k0i = ski + c0 * KTAPS;
    const float* k1i = k0i + KTAPS;
    const ulonglong2* xl = reinterpret_cast<const ulonglong2*>(xw + l * XW_PITCH);

    // 8 independent f32x2 chains: {2 ch} x {re,im} x {even/odd tap-quad half}.
    // Each f32x2 pair accumulates taps (k, k+1) directly: the x LDS.128 halves
    // ARE the multiplicand pairs — no packing movs.
    u64 rA0 = 0, rB0 = 0, iA0 = 0, iB0 = 0;
    u64 rA1 = 0, rB1 = 0, iA1 = 0, iB1 = 0;

    #pragma unroll 4
    for (int k4 = 0; k4 < KTAPS / 4; k4++) {
        const ulonglong2 xv = xl[k4];                      // taps 4k4..4k4+3 (conflict-free)
        const ulonglong2 a0 = *reinterpret_cast<const ulonglong2*>(k0r + 4 * k4); // uniform bcast
        const ulonglong2 b0 = *reinterpret_cast<const ulonglong2*>(k0i + 4 * k4);
        const ulonglong2 a1 = *reinterpret_cast<const ulonglong2*>(k1r + 4 * k4);
        const ulonglong2 b1 = *reinterpret_cast<const ulonglong2*>(k1i + 4 * k4);
        ffma2(rA0, a0.x, xv.x);  ffma2(rB0, a0.y, xv.y);
        ffma2(iA0, b0.x, xv.x);  ffma2(iB0, b0.y, xv.y);
        ffma2(rA1, a1.x, xv.x);  ffma2(rB1, a1.y, xv.y);
        ffma2(iA1, b1.x, xv.x);  ffma2(iB1, b1.y, xv.y);
    }

    const float re0 = hsum2(add2(rA0, rB0));
    const float im0 = hsum2(add2(iA0, iB0));
    const float re1 = hsum2(add2(rA1, rB1));
    const float im1 = hsum2(add2(iA1, iB1));

    const int sg = g * S_PER_BLK + l;
    if (sg < SOUT) {
        const int c = h * CH_PER_CTA + c0;
        const size_t idx0 = (size_t)(b * CHANS + c) * SOUT + sg;
        if (mode == 0) {                     // real part only (B,C,S)
            out[idx0]        = re0;
            out[idx0 + SOUT] = re1;
        } else if (mode == 1) {              // planar (2,B,C,S)
            out[idx0]               = re0;
            out[idx0 + SOUT]        = re1;
            out[NOUT + idx0]        = im0;
            out[NOUT + idx0 + SOUT] = im1;
        } else {                             // interleaved complex64
            float2* o2 = reinterpret_cast<float2*>(out);
            o2[idx0]        = make_float2(re0, im0);
            o2[idx0 + SOUT] = make_float2(re1, im1);
        }
    }
}

extern "C" void kernel_launch(void* const* d_in, const int* in_sizes, int n_in,
                              void* d_out, int out_size)
{
    const float* x  = (const float*)d_in[0];   // (32, 1, 16000) f32
    const float* kr = (const float*)d_in[1];   // (40, 128) f32
    const float* ki = (const float*)d_in[2];   // (40, 128) f32
    float* out = (float*)d_out;

    int mode;
    if (out_size == NOUT)          mode = 0;
    else if (out_size == 2 * NOUT) mode = 1;
    else                           mode = 2;

    cudaFuncSetAttribute(ISAC_33062658244828_kernel,
                         cudaFuncAttributeMaxDynamicSharedMemorySize, SMEM_BYTES);

    dim3 grid(GROUPS, BATCH, CH_SPLIT);
    ISAC_33062658244828_kernel<<<grid, NTHREADS, SMEM_BYTES>>>(x, kr, ki, out, mode);
}